// round 12
// baseline (speedup 1.0000x reference)
#include <cuda_runtime.h>
#include <math.h>

#define NN 3000
#define EE 48000
#define K1 1500
#define K2 750
#define KWP 384
#define NP2 768
#define GRID 148
#define TPB 512

// ---------------- device memory pools ----------------
static const size_t Z_A1   = 0;                      // 1500*1500
static const size_t Z_AGG1 = Z_A1   + 2250000;
static const size_t Z_AGG2 = Z_AGG1 + 96000;
static const size_t Z_AGG3 = Z_AGG2 + 48000;
static const size_t Z_DEG1 = Z_AGG3 + 96000;
static const size_t Z_DEG2 = Z_DEG1 + 1504;
static const size_t ZTOT   = Z_DEG2 + 752;
static const size_t F_A2   = ZTOT;
static const size_t F_XW   = F_A2   + 562500;
static const size_t F_XS   = F_XW   + 192000;
static const size_t F_H0   = F_XS   + 192000;
static const size_t F_H1   = F_H0   + 192000;
static const size_t F_H2   = F_H1   + 96000;
static const size_t F_HUP  = F_H2   + 48000;
static const size_t F_SC   = F_HUP  + 96000;
static const size_t F_TOT  = F_SC   + 3008;

__device__ float g_fpool[F_TOT];

static const size_t IZ_CNT     = 0;
static const size_t IZ_COLCNT  = 3000;
static const size_t IZ_FILL    = 6000;
static const size_t IZ_COLFILL = 9000;
static const size_t IZTOT      = 12000;
static const size_t I_ROWPTR = 12000;
static const size_t I_COLPTR = I_ROWPTR + 3004;
static const size_t I_COLS   = I_COLPTR + 3004;
static const size_t I_CSRC   = I_COLS   + 48000;
static const size_t I_PERM1  = I_CSRC   + 48000;
static const size_t I_PERM2  = I_PERM1  + 1504;
static const size_t I_MAP1   = I_PERM2  + 768;
static const size_t I_MAP2   = I_MAP1   + 3000;
static const size_t I_APT    = I_MAP2   + 1504;
static const size_t I_GPT    = I_APT    + (size_t)KWP * NP2;
static const size_t I_TOT    = I_GPT    + (size_t)KWP * NP2;

__device__ int g_ipool[I_TOT];
__device__ int g_bar[64];

// ---------------- device helpers ----------------

__device__ __forceinline__ void gbar(int p) {
    __syncthreads();
    if (threadIdx.x == 0) {
        __threadfence();
        atomicAdd(&g_bar[p], 1);
        while (((volatile int*)g_bar)[p] < GRID) { }
        __threadfence();
    }
    __syncthreads();
}

__device__ __forceinline__ unsigned f2o(float f) {
    unsigned b = __float_as_uint(f);
    return (b & 0x80000000u) ? ~b : (b | 0x80000000u);
}

// block-0 only: two exclusive scans (512 threads, 6 elems each)
__device__ void phase_scan(char* shm, const int* cnt, int* rowptr,
                           const int* colcnt, int* colptr) {
    int* part = (int*)shm;   // 512 ints
    int tid = threadIdx.x;
    for (int rep = 0; rep < 2; rep++) {
        const int* src = rep ? colcnt : cnt;
        int* dst = rep ? colptr : rowptr;
        int base = tid * 6;
        int loc[6]; int sum = 0;
        #pragma unroll
        for (int q = 0; q < 6; q++) { loc[q] = sum; int v = (base + q < NN) ? src[base + q] : 0; sum += v; }
        part[tid] = sum;
        __syncthreads();
        for (int off = 1; off < TPB; off <<= 1) {
            int t = (tid >= off) ? part[tid - off] : 0;
            __syncthreads();
            part[tid] += t;
            __syncthreads();
        }
        int offset = tid ? part[tid - 1] : 0;
        #pragma unroll
        for (int q = 0; q < 6; q++) if (base + q < NN) dst[base + q] = offset + loc[q];
        if (tid == TPB - 1) dst[NN] = part[TPB - 1];
        __syncthreads();
    }
}

// block-0 only: radix top-k set selection (threshold ties -> lowest index)
__device__ void phase_select(char* shm, const float* score, int n, int k,
                             int* perm, int* map) {
    int* hist = (int*)shm;
    int* eqidx = hist + 256;
    unsigned* uscal = (unsigned*)(eqidx + 3072);
    int* iscal = (int*)(uscal + 1);
    int tid = threadIdx.x;
    if (tid == 0) { uscal[0] = 0; iscal[0] = k; iscal[1] = 0; iscal[2] = 0; }
    __syncthreads();
    for (int shift = 24; shift >= 0; shift -= 8) {
        for (int d = tid; d < 256; d += TPB) hist[d] = 0;
        __syncthreads();
        unsigned pref = uscal[0];
        unsigned hmask = (shift < 24) ? (0xFFFFFFFFu << (shift + 8)) : 0u;
        for (int i = tid; i < n; i += TPB) {
            unsigned u = f2o(score[i]);
            if ((u & hmask) == (pref & hmask)) atomicAdd(&hist[(u >> shift) & 0xFF], 1);
        }
        __syncthreads();
        if (tid == 0) {
            int rem = iscal[0], cum = 0, d = 255;
            for (; d > 0; d--) { if (cum + hist[d] >= rem) break; cum += hist[d]; }
            uscal[0] = pref | ((unsigned)d << shift);
            iscal[0] = rem - cum;
        }
        __syncthreads();
    }
    unsigned T = uscal[0];
    int rem = iscal[0];
    for (int i = tid; i < n; i += TPB) {
        unsigned u = f2o(score[i]);
        if (u > T) { int pos = atomicAdd(&iscal[2], 1); perm[pos] = i; map[i] = pos; }
        else { map[i] = -1; if (u == T) { int e = atomicAdd(&iscal[1], 1); eqidx[e] = i; } }
    }
    __syncthreads();
    int m = iscal[1];
    for (int e = tid; e < m; e += TPB) {
        int id = eqidx[e]; int rank = 0;
        for (int f = 0; f < m; f++) rank += (eqidx[f] < id);
        if (rank < rem) { int pos = atomicAdd(&iscal[2], 1); perm[pos] = id; map[id] = pos; }
    }
}

// lin64: 8-row groups, block-strided
__device__ void phase_lin64(char* shm, const float* H, const float* sc,
                            const int* permOrMap, const float* W, const float* deg,
                            float* XW, float* XS, int n, int pooled, const float* res) {
    float* sh = (float*)shm;   // 8*64
    int tid = threadIdx.x;
    int r = tid >> 6, kc = tid & 63;
    for (int base = blockIdx.x * 8; base < n; base += GRID * 8) {
        __syncthreads();
        int i = base + r;
        float lv = 0.f;
        if (i < n) {
            if (pooled) { int src = permOrMap[i]; lv = H[(size_t)src * 64 + kc] * sc[src]; }
            else { int m = permOrMap[i]; lv = res[(size_t)i * 64 + kc] + (m >= 0 ? H[(size_t)m * 64 + kc] : 0.f); }
        }
        sh[r * 64 + kc] = lv;
        __syncthreads();
        if (i < n) {
            float acc = 0.f;
            #pragma unroll
            for (int k = 0; k < 64; k++) acc += sh[r * 64 + k] * W[k * 64 + kc];
            float di = rsqrtf(deg[i] + 2.f);
            XW[i * 64 + kc] = acc;
            XS[i * 64 + kc] = acc * di;
        }
    }
}

// finalize (C=64) + optional fused score, 8-row groups
__device__ void phase_fin(char* shm, const float* agg, const float* xw,
                          const float* deg, const float* b, float* out, int n,
                          int act, const float* p, float* score) {
    float* part = (float*)shm; float* ppart = part + 16;
    int tid = threadIdx.x;
    int r = tid >> 6, c = tid & 63;
    for (int base = blockIdx.x * 8; base < n; base += GRID * 8) {
        __syncthreads();
        int i = base + r;
        float v = 0.f;
        if (i < n) {
            float di = rsqrtf(deg[i] + 2.f);
            int idx = i * 64 + c;
            v = di * agg[idx] + 2.f * di * di * xw[idx] + b[c];
            if (act) v = tanhf(v);
            out[idx] = v;
        }
        if (p) {
            float pc = p[c];
            float hp = (i < n) ? v * pc : 0.f;
            float pp = (r == 0) ? pc * pc : 0.f;
            #pragma unroll
            for (int off = 16; off > 0; off >>= 1) {
                hp += __shfl_down_sync(0xffffffffu, hp, off);
                pp += __shfl_down_sync(0xffffffffu, pp, off);
            }
            int w = tid >> 5, lane = tid & 31;
            if (lane == 0) { part[w] = hp; ppart[w] = pp; }
            __syncthreads();
            if (tid < 8) {
                int ii = base + tid;
                if (ii < n) {
                    float dot = part[tid * 2] + part[tid * 2 + 1];
                    float pn = ppart[0] + ppart[1];
                    score[ii] = tanhf(dot * rsqrtf(pn));
                }
            }
        }
    }
}

// out[t,c] += sum_s A[s,t]*X[s,c]; 512 threads: 8 groups x 4 outputs over 32-t tiles
__device__ void phase_atx(char* shm, const float* A, const float* X, float* out,
                          int n, int nchunks) {
    float* As = (float*)shm;       // 8*32
    float* Xs = As + 8 * 32;       // 8*64
    int tid = threadIdx.x;
    int c = tid & 63, g = tid >> 6;   // g in 0..7
    int ntiles = (n + 31) / 32;
    int per = (n + nchunks - 1) / nchunks;
    int total = ntiles * nchunks;
    for (int b = blockIdx.x; b < total; b += GRID) {
        int tile = b % ntiles, chunk = b / ntiles;
        int T0 = tile * 32;
        int s_begin = chunk * per;
        int s_end = min(s_begin + per, n);
        float acc[4] = {0.f, 0.f, 0.f, 0.f};
        for (int s0 = s_begin; s0 < s_end; s0 += 8) {
            __syncthreads();
            if (tid < 256) {
                int ss = tid >> 5, tt = tid & 31;
                int gs = s0 + ss, gt2 = T0 + tt;
                As[ss * 32 + tt] = (gs < s_end && gt2 < n) ? A[(size_t)gs * n + gt2] : 0.f;
            }
            {
                int ss = tid >> 6, cc = tid & 63;
                int gs = s0 + ss;
                Xs[ss * 64 + cc] = (gs < s_end) ? X[(size_t)gs * 64 + cc] : 0.f;
            }
            __syncthreads();
            #pragma unroll
            for (int ss = 0; ss < 8; ss++) {
                float xv = Xs[ss * 64 + c];
                #pragma unroll
                for (int k = 0; k < 4; k++) acc[k] += As[ss * 32 + g * 4 + k] * xv;
            }
        }
        #pragma unroll
        for (int k = 0; k < 4; k++) {
            int t = T0 + g * 4 + k;
            if (t < n) atomicAdd(&out[(size_t)t * 64 + c], acc[k]);
        }
    }
}

// dp4a A2 GEMM, 512 threads: 64x64 tiles, 2x4 per thread
__device__ void phase_dp4a(char* shm, const int* Apt, const int* Gpt,
                           const float* A1v, const int* perm, float* A2, float* deg2) {
    int* As = (int*)shm;        // 8*68
    int* Bs = As + 544;         // 8*68
    int* prs = Bs + 544;        // 64
    int* pcs = prs + 64;        // 64
    float* csum = (float*)(pcs + 64);
    int tid = threadIdx.x;
    int tx = tid & 15, ty = tid >> 4;   // ty in 0..31
    for (int b = blockIdx.x; b < 144; b += GRID) {
        int row0 = (b / 12) * 64, col0 = (b % 12) * 64;
        __syncthreads();
        if (tid < 64) { prs[tid] = (row0 + tid < K2) ? perm[row0 + tid] : 0; csum[tid] = 0.f; }
        else if (tid < 128) { int c = tid - 64; pcs[c] = (col0 + c < K2) ? perm[col0 + c] : 0; }
        __syncthreads();
        int acc[2][4] = {};
        for (int k0 = 0; k0 < KWP; k0 += 8) {
            {
                int w = tid >> 6, c = tid & 63;
                As[w * 68 + c] = Apt[(k0 + w) * NP2 + row0 + c];
                Bs[w * 68 + c] = Gpt[(k0 + w) * NP2 + col0 + c];
            }
            __syncthreads();
            #pragma unroll
            for (int kk = 0; kk < 8; kk++) {
                int a0 = As[kk * 68 + ty * 2];
                int a1 = As[kk * 68 + ty * 2 + 1];
                int4 b4 = *reinterpret_cast<const int4*>(&Bs[kk * 68 + tx * 4]);
                int bb[4] = {b4.x, b4.y, b4.z, b4.w};
                #pragma unroll
                for (int j = 0; j < 4; j++) {
                    acc[0][j] = __dp4a(a0, bb[j], acc[0][j]);
                    acc[1][j] = __dp4a(a1, bb[j], acc[1][j]);
                }
            }
            __syncthreads();
        }
        float cj[4] = {0.f, 0.f, 0.f, 0.f};
        #pragma unroll
        for (int i2 = 0; i2 < 2; i2++) {
            int gr = row0 + ty * 2 + i2;
            if (gr >= K2) continue;
            int ar = prs[ty * 2 + i2];
            #pragma unroll
            for (int j = 0; j < 4; j++) {
                int gc = col0 + tx * 4 + j;
                if (gc >= K2) continue;
                float val = (gr == gc) ? 0.f
                          : (float)acc[i2][j] + 2.f * A1v[(size_t)ar * K1 + pcs[tx * 4 + j]];
                A2[(size_t)gr * K2 + gc] = val;
                cj[j] += val;
            }
        }
        #pragma unroll
        for (int j = 0; j < 4; j++) atomicAdd(&csum[tx * 4 + j], cj[j]);
        __syncthreads();
        if (tid < 64 && col0 + tid < K2) atomicAdd(&deg2[col0 + tid], csum[tid]);
    }
}

// ---------------- the persistent mega-kernel ----------------

__global__ void __launch_bounds__(TPB, 1)
mega(const float* __restrict__ x, const int* __restrict__ ei,
     const float* __restrict__ W0, const float* __restrict__ b0,
     const float* __restrict__ W1, const float* __restrict__ b1,
     const float* __restrict__ W2, const float* __restrict__ b2,
     const float* __restrict__ p1, const float* __restrict__ p2,
     const float* __restrict__ Wu0, const float* __restrict__ bu0,
     const float* __restrict__ Wu1, const float* __restrict__ bu1,
     float* __restrict__ out) {
    __shared__ __align__(16) char shm[14336];
    float* fp = g_fpool;
    int* ip = g_ipool;
    float *A1 = fp + Z_A1, *AGG1 = fp + Z_AGG1, *AGG2 = fp + Z_AGG2,
          *AGG3 = fp + Z_AGG3, *DEG1 = fp + Z_DEG1, *DEG2 = fp + Z_DEG2,
          *A2 = fp + F_A2, *XW = fp + F_XW, *XS = fp + F_XS,
          *H0 = fp + F_H0, *H1 = fp + F_H1, *H2 = fp + F_H2, *HUP = fp + F_HUP,
          *SC = fp + F_SC;
    int *CNT = ip + IZ_CNT, *COLCNT = ip + IZ_COLCNT, *FILL = ip + IZ_FILL,
        *COLFILL = ip + IZ_COLFILL, *ROWPTR = ip + I_ROWPTR, *COLPTR = ip + I_COLPTR,
        *COLS = ip + I_COLS, *CSRC = ip + I_CSRC, *PERM1 = ip + I_PERM1,
        *PERM2 = ip + I_PERM2, *MAP1 = ip + I_MAP1, *MAP2 = ip + I_MAP2,
        *APT = ip + I_APT, *GPT = ip + I_GPT;

    int tid = threadIdx.x, bid = blockIdx.x;
    int gt = bid * TPB + tid;

    // P0: zero Z and IZ regions
    {
        float4 zf = {0.f, 0.f, 0.f, 0.f};
        for (int i = gt; i < (int)(ZTOT / 4); i += GRID * TPB) reinterpret_cast<float4*>(fp)[i] = zf;
        int4 zi = {0, 0, 0, 0};
        for (int i = gt; i < (int)(IZTOT / 4); i += GRID * TPB) reinterpret_cast<int4*>(ip)[i] = zi;
    }
    gbar(0);

    // P1: degree count
    for (int e = gt; e < EE; e += GRID * TPB) {
        atomicAdd(&CNT[ei[e]], 1);
        atomicAdd(&COLCNT[ei[EE + e]], 1);
    }
    gbar(1);

    // P2: block 0 -> scans; blocks 1..147 -> lin0
    if (bid == 0) {
        phase_scan(shm, CNT, ROWPTR, COLCNT, COLPTR);
    } else {
        float* sh = (float*)shm;   // 8*16
        int r = tid >> 6, c = tid & 63;
        for (int base = (bid - 1) * 8; base < NN; base += (GRID - 1) * 8) {
            __syncthreads();
            if (tid < 128) {
                int rr = tid >> 4, k = tid & 15;
                int i = base + rr;
                sh[rr * 16 + k] = (i < NN) ? x[i * 16 + k] : 0.f;
            }
            __syncthreads();
            int i = base + r;
            if (i < NN) {
                float acc = 0.f;
                #pragma unroll
                for (int k = 0; k < 16; k++) acc += sh[r * 16 + k] * W0[k * 64 + c];
                float di = rsqrtf((float)COLCNT[i] + 2.f);
                XW[i * 64 + c] = acc;
                XS[i * 64 + c] = acc * di;
            }
        }
    }
    gbar(2);

    // P3: fill CSR + CSC
    for (int e = gt; e < EE; e += GRID * TPB) {
        int s = ei[e], t = ei[EE + e];
        int p = ROWPTR[s] + atomicAdd(&FILL[s], 1);
        COLS[p] = t;
        int q = COLPTR[t] + atomicAdd(&COLFILL[t], 1);
        CSRC[q] = s;
    }
    gbar(3);

    // P4: GCN0 (CSC gather) + tanh + fused score1
    {
        float* part = (float*)shm; float* ppart = part + 16;
        int r = tid >> 6, c = tid & 63;
        for (int base = bid * 8; base < NN; base += GRID * 8) {
            __syncthreads();
            int i = base + r;
            float v = 0.f;
            if (i < NN) {
                float acc = 0.f;
                int q0 = COLPTR[i], q1 = COLPTR[i + 1];
                for (int q = q0; q < q1; q++) acc += XS[CSRC[q] * 64 + c];
                float di = rsqrtf((float)COLCNT[i] + 2.f);
                v = tanhf(di * acc + 2.f * di * di * XW[i * 64 + c] + b0[c]);
                H0[i * 64 + c] = v;
            }
            float pc = p1[c];
            float hp = (i < NN) ? v * pc : 0.f;
            float pp = (r == 0) ? pc * pc : 0.f;
            #pragma unroll
            for (int off = 16; off > 0; off >>= 1) {
                hp += __shfl_down_sync(0xffffffffu, hp, off);
                pp += __shfl_down_sync(0xffffffffu, pp, off);
            }
            int w = tid >> 5, lane = tid & 31;
            if (lane == 0) { part[w] = hp; ppart[w] = pp; }
            __syncthreads();
            if (tid < 8) {
                int ii = base + tid;
                if (ii < NN) {
                    float dot = part[tid * 2] + part[tid * 2 + 1];
                    float pn = ppart[0] + ppart[1];
                    SC[ii] = tanhf(dot * rsqrtf(pn));
                }
            }
        }
    }
    gbar(4);

    // P5: select1
    if (bid == 0) phase_select(shm, SC, NN, K1, PERM1, MAP1);
    gbar(5);

    // P6: A1 = (B@B + 2B)[perm1 x perm1] off-diag + DEG1
    for (int e = gt; e < EE; e += GRID * TPB) {
        int s = ei[e], t = ei[EE + e];
        if (s == t) continue;
        int i = MAP1[s];
        if (i < 0) continue;
        int j0 = MAP1[t];
        if (j0 >= 0 && j0 != i) {
            atomicAdd(&A1[(size_t)i * K1 + j0], 2.0f);
            atomicAdd(&DEG1[j0], 2.0f);
        }
        int q0 = ROWPTR[t], q1 = ROWPTR[t + 1];
        for (int q = q0; q < q1; q++) {
            int u = COLS[q];
            if (u == t) continue;
            int j = MAP1[u];
            if (j < 0 || j == i) continue;
            atomicAdd(&A1[(size_t)i * K1 + j], 1.0f);
            atomicAdd(&DEG1[j], 1.0f);
        }
    }
    gbar(6);

    // P7: linpool1
    phase_lin64(shm, H0, SC, PERM1, W1, DEG1, XW, XS, K1, 1, nullptr);
    gbar(7);

    // P8: AGG1 = A1^T @ XS
    phase_atx(shm, A1, XS, AGG1, K1, 3);
    gbar(8);

    // P9: finalize GCN1 + score2
    phase_fin(shm, AGG1, XW, DEG1, b1, H1, K1, 1, p2, SC);
    gbar(9);

    // P10: select2
    if (bid == 0) phase_select(shm, SC, K1, K2, PERM2, MAP2);
    gbar(10);

    // P11: pack int8 operands
    {
        const int half = KWP * NP2;
        for (int idx = gt; idx < 2 * half; idx += GRID * TPB) {
            int sel = (idx >= half) ? 1 : 0;
            int l = idx - sel * half;
            int w = l / NP2, i = l - w * NP2;
            int v = 0;
            if (i < K2) {
                int pi = PERM2[i];
                if (sel == 0) {
                    const float* row = A1 + (size_t)pi * K1;
                    #pragma unroll
                    for (int q = 0; q < 4; q++) {
                        int kq = 4 * w + q;
                        int bb = (kq < K1) ? (int)row[kq] : 0;
                        v |= (bb & 0xFF) << (8 * q);
                    }
                } else {
                    #pragma unroll
                    for (int q = 0; q < 4; q++) {
                        int kq = 4 * w + q;
                        int bb = (kq < K1) ? (int)A1[(size_t)kq * K1 + pi] : 0;
                        v |= (bb & 0xFF) << (8 * q);
                    }
                }
            }
            if (sel == 0) APT[w * NP2 + i] = v; else GPT[w * NP2 + i] = v;
        }
    }
    gbar(11);

    // P12: A2 via dp4a GEMM + DEG2
    phase_dp4a(shm, APT, GPT, A1, PERM2, A2, DEG2);
    gbar(12);

    // P13: linpool2
    phase_lin64(shm, H1, SC, PERM2, W2, DEG2, XW, XS, K2, 1, nullptr);
    gbar(13);

    // P14: AGG2 = A2^T @ XS
    phase_atx(shm, A2, XS, AGG2, K2, 6);
    gbar(14);

    // P15: finalize GCN2 -> H2
    phase_fin(shm, AGG2, XW, DEG2, b2, H2, K2, 1, nullptr, nullptr);
    gbar(15);

    // P16: linup64 (res1 + scatter-back of H2)
    phase_lin64(shm, H2, nullptr, MAP2, Wu0, DEG1, XW, XS, K1, 0, H1);
    gbar(16);

    // P17: AGG3 = A1^T @ XS
    phase_atx(shm, A1, XS, AGG3, K1, 3);
    gbar(17);

    // P18: finalize up-GCN -> HUP
    phase_fin(shm, AGG3, XW, DEG1, bu0, HUP, K1, 1, nullptr, nullptr);
    gbar(18);

    // P19: linup16 -> 16-wide XW/XS (32-row groups)
    {
        float* sh = (float*)shm;  // 32*64
        for (int base = bid * 32; base < NN; base += GRID * 32) {
            __syncthreads();
            #pragma unroll
            for (int q = 0; q < 4; q++) {
                int li = tid + q * TPB;
                int r = li >> 6, k = li & 63;
                int i = base + r;
                float lv = 0.f;
                if (i < NN) {
                    int m = MAP1[i];
                    lv = H0[(size_t)i * 64 + k] + (m >= 0 ? HUP[(size_t)m * 64 + k] : 0.f);
                }
                sh[r * 64 + k] = lv;
            }
            __syncthreads();
            int r = tid >> 4, c = tid & 15;
            int i = base + r;
            if (i < NN) {
                float acc = 0.f;
                #pragma unroll
                for (int k = 0; k < 64; k++) acc += sh[r * 64 + k] * Wu1[k * 16 + c];
                float di = rsqrtf((float)COLCNT[i] + 2.f);
                XW[i * 16 + c] = acc;
                XS[i * 16 + c] = acc * di;
            }
        }
    }
    gbar(19);

    // P20: final GCN (CSC gather, C=16, no activation) -> out
    {
        int r = tid >> 4, c = tid & 15;
        for (int base = bid * 32; base < NN; base += GRID * 32) {
            int i = base + r;
            if (i >= NN) continue;
            float acc = 0.f;
            int q0 = COLPTR[i], q1 = COLPTR[i + 1];
            for (int q = q0; q < q1; q++) acc += XS[CSRC[q] * 16 + c];
            float di = rsqrtf((float)COLCNT[i] + 2.f);
            out[i * 16 + c] = di * acc + 2.f * di * di * XW[i * 16 + c] + bu1[c];
        }
    }
}

// ---------------- host ----------------

extern "C" void kernel_launch(void* const* d_in, const int* in_sizes, int n_in,
                              void* d_out, int out_size) {
    int* bar = nullptr;
    cudaGetSymbolAddress((void**)&bar, g_bar);

    const float* x   = (const float*)d_in[0];
    const int*   ei  = (const int*)  d_in[1];
    const float* W0  = (const float*)d_in[2];
    const float* b0  = (const float*)d_in[3];
    const float* W1  = (const float*)d_in[4];
    const float* b1  = (const float*)d_in[5];
    const float* W2  = (const float*)d_in[6];
    const float* b2  = (const float*)d_in[7];
    const float* p1  = (const float*)d_in[8];
    const float* p2  = (const float*)d_in[9];
    const float* Wu0 = (const float*)d_in[10];
    const float* bu0 = (const float*)d_in[11];
    const float* Wu1 = (const float*)d_in[12];
    const float* bu1 = (const float*)d_in[13];
    float* out = (float*)d_out;

    cudaMemsetAsync(bar, 0, 64 * sizeof(int), 0);
    mega<<<GRID, TPB>>>(x, ei, W0, b0, W1, b1, W2, b2, p1, p2,
                        Wu0, bu0, Wu1, bu1, out);
}

// round 15
// speedup vs baseline: 1.2204x; 1.2204x over previous
#include <cuda_runtime.h>
#include <math.h>

#define NN 3000
#define EE 48000
#define K1 1500
#define K2 750
#define KWP 384
#define NP2 768

// ---------------- float pool ----------------
static const size_t Z_A1   = 0;                      // 1500*1500
static const size_t Z_AGG1 = Z_A1   + 2250000;       // 1500*64
static const size_t Z_AGG2 = Z_AGG1 + 96000;         // 750*64
static const size_t Z_AGG3 = Z_AGG2 + 48000;         // 1500*64
static const size_t Z_DEG1 = Z_AGG3 + 96000;         // 1504
static const size_t Z_DEG2 = Z_DEG1 + 1504;          // 752
static const size_t ZTOT   = Z_DEG2 + 752;
static const size_t F_A2   = ZTOT;                   // 750*750
static const size_t F_XW   = F_A2   + 562500;
static const size_t F_XS   = F_XW   + 192000;
static const size_t F_H0   = F_XS   + 192000;
static const size_t F_H1   = F_H0   + 192000;
static const size_t F_H2   = F_H1   + 96000;
static const size_t F_HUP  = F_H2   + 48000;
static const size_t F_SC   = F_HUP  + 96000;
static const size_t F_TOT  = F_SC   + 3008;

__device__ float g_fpool[F_TOT];

// ---------------- int pool; first IZTOT zeroed each replay ----------------
static const size_t IZ_CNT     = 0;      // 3000
static const size_t IZ_COLCNT  = 3000;   // 3000
static const size_t IZ_FILL    = 6000;   // 3000
static const size_t IZ_COLFILL = 9000;   // 3000
static const size_t IZ_CTR     = 12000;  // 128 counters:
                                          // [0]      gcn0 block ctr
                                          // [1..47]  atxfin1 tile ctrs (47)
                                          // [48]     atxfin1 done ctr
                                          // [49..72] atxfin2 tile ctrs (24)
                                          // [73..119] atxfin3 tile ctrs (47)
static const size_t IZTOT      = 12128;
static const size_t I_ROWPTR = IZTOT;                // 3004
static const size_t I_COLPTR = I_ROWPTR + 3004;
static const size_t I_COLS   = I_COLPTR + 3004;      // 48000
static const size_t I_CSRC   = I_COLS   + 48000;     // 48000
static const size_t I_PERM1  = I_CSRC   + 48000;     // 1504
static const size_t I_PERM2  = I_PERM1  + 1504;      // 768
static const size_t I_MAP1   = I_PERM2  + 768;       // 3000
static const size_t I_MAP2   = I_MAP1   + 3000;      // 1504
static const size_t I_APT    = I_MAP2   + 1504;
static const size_t I_GPT    = I_APT    + (size_t)KWP * NP2;
static const size_t I_TOT    = I_GPT    + (size_t)KWP * NP2;

__device__ int g_ipool[I_TOT];

// ---------------- device helpers ----------------

__device__ __forceinline__ unsigned f2o(float f) {
    unsigned b = __float_as_uint(f);
    return (b & 0x80000000u) ? ~b : (b | 0x80000000u);
}

// 256-thread radix top-k set selection (threshold ties -> lowest index)
__device__ void dev_select(const float* __restrict__ score, int n, int k,
                           int* __restrict__ perm, int* __restrict__ map) {
    __shared__ int hist[256];
    __shared__ int eqidx[3072];
    __shared__ unsigned sh_prefix;
    __shared__ int sh_rem, eqn, poscnt;
    int tid = threadIdx.x;
    if (tid == 0) { sh_prefix = 0; sh_rem = k; eqn = 0; poscnt = 0; }
    __syncthreads();
    for (int shift = 24; shift >= 0; shift -= 8) {
        hist[tid] = 0;
        __syncthreads();
        unsigned pref = sh_prefix;
        unsigned hmask = (shift < 24) ? (0xFFFFFFFFu << (shift + 8)) : 0u;
        for (int i = tid; i < n; i += 256) {
            unsigned u = f2o(score[i]);
            if ((u & hmask) == (pref & hmask)) atomicAdd(&hist[(u >> shift) & 0xFF], 1);
        }
        __syncthreads();
        if (tid == 0) {
            int rem = sh_rem, cum = 0, d = 255;
            for (; d > 0; d--) { if (cum + hist[d] >= rem) break; cum += hist[d]; }
            sh_prefix = pref | ((unsigned)d << shift);
            sh_rem = rem - cum;
        }
        __syncthreads();
    }
    unsigned T = sh_prefix;
    int rem = sh_rem;
    for (int i = tid; i < n; i += 256) {
        unsigned u = f2o(score[i]);
        if (u > T) { int pos = atomicAdd(&poscnt, 1); perm[pos] = i; map[i] = pos; }
        else { map[i] = -1; if (u == T) { int e = atomicAdd(&eqn, 1); eqidx[e] = i; } }
    }
    __syncthreads();
    int m = eqn;
    for (int e = tid; e < m; e += 256) {
        int id = eqidx[e]; int rank = 0;
        for (int f = 0; f < m; f++) rank += (eqidx[f] < id);
        if (rank < rem) { int pos = atomicAdd(&poscnt, 1); perm[pos] = id; map[id] = pos; }
    }
}

// ---------------- kernels ----------------

__global__ void k_count(const int* __restrict__ ei, int* cnt, int* colcnt) {
    int e = blockIdx.x * blockDim.x + threadIdx.x;
    if (e >= EE) return;
    atomicAdd(&cnt[ei[e]], 1);
    atomicAdd(&colcnt[ei[EE + e]], 1);
}

__global__ void k_scan2(const int* __restrict__ cnt, int* rowptr,
                        const int* __restrict__ colcnt, int* colptr) {
    __shared__ int part[1024];
    int tid = threadIdx.x;
    int base = tid * 3;
    for (int rep = 0; rep < 2; rep++) {
        const int* src = rep ? colcnt : cnt;
        int* dst = rep ? colptr : rowptr;
        int l0, l1, l2, sum = 0, v;
        l0 = sum; v = (base + 0 < NN) ? src[base + 0] : 0; sum += v;
        l1 = sum; v = (base + 1 < NN) ? src[base + 1] : 0; sum += v;
        l2 = sum; v = (base + 2 < NN) ? src[base + 2] : 0; sum += v;
        part[tid] = sum;
        __syncthreads();
        for (int off = 1; off < 1024; off <<= 1) {
            int t = (tid >= off) ? part[tid - off] : 0;
            __syncthreads();
            part[tid] += t;
            __syncthreads();
        }
        int offset = (tid > 0) ? part[tid - 1] : 0;
        if (base + 0 < NN) dst[base + 0] = offset + l0;
        if (base + 1 < NN) dst[base + 1] = offset + l1;
        if (base + 2 < NN) dst[base + 2] = offset + l2;
        if (tid == 1023) dst[NN] = part[1023];
        __syncthreads();
    }
}

__global__ void k_fill(const int* __restrict__ ei, const int* __restrict__ rowptr,
                       const int* __restrict__ colptr, int* fill, int* colfill,
                       int* cols, int* csrc) {
    int e = blockIdx.x * blockDim.x + threadIdx.x;
    if (e >= EE) return;
    int s = ei[e], t = ei[EE + e];
    int p = rowptr[s] + atomicAdd(&fill[s], 1);
    cols[p] = t;
    int q = colptr[t] + atomicAdd(&colfill[t], 1);
    csrc[q] = s;
}

__global__ void k_lin0(const float* __restrict__ x, const float* __restrict__ W,
                       const int* __restrict__ colcnt, float* __restrict__ XW,
                       float* __restrict__ XS) {
    __shared__ float sh[4][16];
    int tid = threadIdx.x;
    int base = blockIdx.x * 4;
    if (tid < 64) {
        int r = tid >> 4, k = tid & 15;
        int i = base + r;
        sh[r][k] = (i < NN) ? x[i * 16 + k] : 0.f;
    }
    __syncthreads();
    int r = tid >> 6, c = tid & 63;
    int i = base + r;
    if (i >= NN) return;
    float acc = 0.f;
    #pragma unroll
    for (int k = 0; k < 16; k++) acc += sh[r][k] * W[k * 64 + c];
    float di = rsqrtf((float)colcnt[i] + 2.f);
    XW[i * 64 + c] = acc;
    XS[i * 64 + c] = acc * di;
}

// GCN0 + score1 + fused select1 (last-block-runs-select)
__global__ void k_gcn0_sel(const int* __restrict__ colptr, const int* __restrict__ csrc,
                           const float* __restrict__ XS, const float* __restrict__ XW,
                           const int* __restrict__ colcnt, const float* __restrict__ b,
                           float* __restrict__ H, const float* __restrict__ p,
                           float* __restrict__ score, int* ctr,
                           int* perm, int* map) {
    __shared__ float part[8], ppart[8];
    __shared__ int winner;
    int tid = threadIdx.x;
    int r = tid >> 6, c = tid & 63;
    int i = blockIdx.x * 4 + r;
    float v = 0.f;
    if (i < NN) {
        float acc = 0.f;
        int p0 = colptr[i], p1 = colptr[i + 1];
        for (int q = p0; q < p1; q++) acc += XS[csrc[q] * 64 + c];
        float di = rsqrtf((float)colcnt[i] + 2.f);
        v = tanhf(di * acc + 2.f * di * di * XW[i * 64 + c] + b[c]);
        H[i * 64 + c] = v;
    }
    float pc = p[c];
    float hp = (i < NN) ? v * pc : 0.f;
    float pp = (r == 0) ? pc * pc : 0.f;
    #pragma unroll
    for (int off = 16; off > 0; off >>= 1) {
        hp += __shfl_down_sync(0xffffffffu, hp, off);
        pp += __shfl_down_sync(0xffffffffu, pp, off);
    }
    int w = tid >> 5, lane = tid & 31;
    if (lane == 0) { part[w] = hp; ppart[w] = pp; }
    __syncthreads();
    if (tid < 4) {
        int ii = blockIdx.x * 4 + tid;
        if (ii < NN) {
            float dot = part[tid * 2] + part[tid * 2 + 1];
            float pn = ppart[0] + ppart[1];
            score[ii] = tanhf(dot * rsqrtf(pn));
        }
    }
    // completion -> last block runs select1
    __threadfence();
    __syncthreads();
    if (tid == 0) winner = (atomicAdd(ctr, 1) == (int)gridDim.x - 1);
    __syncthreads();
    if (winner) {
        __threadfence();
        dev_select(score, NN, K1, perm, map);
    }
}

__global__ void k_bb2(const int* __restrict__ ei, const int* __restrict__ rowptr,
                      const int* __restrict__ cols, const int* __restrict__ map,
                      float* A1v, float* deg, int nsub) {
    int e = blockIdx.x * blockDim.x + threadIdx.x;
    if (e >= EE) return;
    int s = ei[e], t = ei[EE + e];
    if (s == t) return;
    int i = map[s];
    if (i < 0) return;
    int j0 = map[t];
    if (j0 >= 0 && j0 != i) {
        atomicAdd(&A1v[(size_t)i * nsub + j0], 2.0f);
        atomicAdd(&deg[j0], 2.0f);
    }
    int p0 = rowptr[t], p1 = rowptr[t + 1];
    for (int p = p0; p < p1; p++) {
        int u = cols[p];
        if (u == t) continue;
        int j = map[u];
        if (j < 0 || j == i) continue;
        atomicAdd(&A1v[(size_t)i * nsub + j], 1.0f);
        atomicAdd(&deg[j], 1.0f);
    }
}

__global__ void k_linpool(const float* __restrict__ H, const float* __restrict__ sc,
                          const int* __restrict__ perm, const float* __restrict__ W,
                          const float* __restrict__ deg, float* __restrict__ XW,
                          float* __restrict__ XS, int n) {
    __shared__ float sh[4][64];
    int tid = threadIdx.x;
    int base = blockIdx.x * 4;
    int r = tid >> 6, kc = tid & 63;
    int i = base + r;
    float lv = 0.f;
    if (i < n) { int src = perm[i]; lv = H[(size_t)src * 64 + kc] * sc[src]; }
    sh[r][kc] = lv;
    __syncthreads();
    if (i >= n) return;
    float acc = 0.f;
    #pragma unroll
    for (int k = 0; k < 64; k++) acc += sh[r][k] * W[k * 64 + kc];
    float di = rsqrtf(deg[i] + 2.f);
    XW[i * 64 + kc] = acc;
    XS[i * 64 + kc] = acc * di;
}

__global__ void k_linup64(const float* __restrict__ res, const float* __restrict__ up,
                          const int* __restrict__ map, const float* __restrict__ W,
                          const float* __restrict__ deg, float* __restrict__ XW,
                          float* __restrict__ XS, int n) {
    __shared__ float sh[4][64];
    int tid = threadIdx.x;
    int base = blockIdx.x * 4;
    int r = tid >> 6, kc = tid & 63;
    int i = base + r;
    float lv = 0.f;
    if (i < n) {
        int m = map[i];
        lv = res[(size_t)i * 64 + kc] + (m >= 0 ? up[(size_t)m * 64 + kc] : 0.f);
    }
    sh[r][kc] = lv;
    __syncthreads();
    if (i >= n) return;
    float acc = 0.f;
    #pragma unroll
    for (int k = 0; k < 64; k++) acc += sh[r][k] * W[k * 64 + kc];
    float di = rsqrtf(deg[i] + 2.f);
    XW[i * 64 + kc] = acc;
    XS[i * 64 + kc] = acc * di;
}

__global__ void k_linup16(const float* __restrict__ res, const float* __restrict__ up,
                          const int* __restrict__ map, const float* __restrict__ W,
                          const int* __restrict__ colcnt, float* __restrict__ XW,
                          float* __restrict__ XS) {
    __shared__ float sh[16][64];
    int tid = threadIdx.x;
    int base = blockIdx.x * 16;
    #pragma unroll
    for (int q = 0; q < 4; q++) {
        int li = tid + q * 256;
        int r = li >> 6, k = li & 63;
        int i = base + r;
        float lv = 0.f;
        if (i < NN) {
            int m = map[i];
            lv = res[(size_t)i * 64 + k] + (m >= 0 ? up[(size_t)m * 64 + k] : 0.f);
        }
        sh[r][k] = lv;
    }
    __syncthreads();
    int r = tid >> 4, c = tid & 15;
    int i = base + r;
    if (i >= NN) return;
    float acc = 0.f;
    #pragma unroll
    for (int k = 0; k < 64; k++) acc += sh[r][k] * W[k * 16 + c];
    float di = rsqrtf((float)colcnt[i] + 2.f);
    XW[i * 16 + c] = acc;
    XS[i * 16 + c] = acc * di;
}

__global__ void k_gcnF(const int* __restrict__ colptr, const int* __restrict__ csrc,
                       const float* __restrict__ XS, const float* __restrict__ XW,
                       const int* __restrict__ colcnt, const float* __restrict__ b,
                       float* __restrict__ out) {
    int tid = threadIdx.x;
    int r = tid >> 4, c = tid & 15;
    int i = blockIdx.x * 16 + r;
    if (i >= NN) return;
    float acc = 0.f;
    int p0 = colptr[i], p1 = colptr[i + 1];
    for (int q = p0; q < p1; q++) acc += XS[csrc[q] * 16 + c];
    float di = rsqrtf((float)colcnt[i] + 2.f);
    out[i * 16 + c] = di * acc + 2.f * di * di * XW[i * 16 + c] + b[c];
}

// fused: A^T@X accumulate + per-tile finalize(+score) + optional last-tile select
// grid (ntiles, nchunks), 256 threads
__global__ void k_atxfin(const float* __restrict__ A, const float* __restrict__ X,
                         float* agg, int n, const float* __restrict__ xw,
                         const float* __restrict__ deg, const float* __restrict__ b,
                         float* __restrict__ outH, int act,
                         const float* __restrict__ p, float* score,
                         int* tilectr, int* donectr, int selK,
                         int* perm, int* map) {
    __shared__ float As[8][32];
    __shared__ float Xs[8][64];
    __shared__ float part[8], ppart[8];
    __shared__ int lastTile, lastAll;
    int tid = threadIdx.x;
    int c = tid & 63, g = tid >> 6;
    int tile = blockIdx.x, nchunks = gridDim.y;
    int T0 = tile * 32;
    int per = (n + nchunks - 1) / nchunks;
    int s_begin = blockIdx.y * per;
    int s_end = min(s_begin + per, n);
    float acc[8] = {0.f, 0.f, 0.f, 0.f, 0.f, 0.f, 0.f, 0.f};
    for (int s0 = s_begin; s0 < s_end; s0 += 8) {
        {
            int ss = tid >> 5, tt = tid & 31;
            int gs = s0 + ss, gt = T0 + tt;
            As[ss][tt] = (gs < s_end && gt < n) ? A[(size_t)gs * n + gt] : 0.f;
        }
        #pragma unroll
        for (int q = 0; q < 2; q++) {
            int li = tid + q * 256;
            int ss = li >> 6, cc = li & 63;
            int gs = s0 + ss;
            Xs[ss][cc] = (gs < s_end) ? X[(size_t)gs * 64 + cc] : 0.f;
        }
        __syncthreads();
        #pragma unroll
        for (int ss = 0; ss < 8; ss++) {
            float xv = Xs[ss][c];
            #pragma unroll
            for (int k = 0; k < 8; k++) acc[k] += As[ss][g * 8 + k] * xv;
        }
        __syncthreads();
    }
    #pragma unroll
    for (int k = 0; k < 8; k++) {
        int t = T0 + g * 8 + k;
        if (t < n) atomicAdd(&agg[(size_t)t * 64 + c], acc[k]);
    }
    // tile completion
    __threadfence();
    __syncthreads();
    if (tid == 0) lastTile = (atomicAdd(&tilectr[tile], 1) == nchunks - 1);
    __syncthreads();
    if (!lastTile) return;
    __threadfence();
    // finalize this tile's 32 rows (8 groups of 4)
    int r = tid >> 6;
    for (int it = 0; it < 8; it++) {
        __syncthreads();
        int i = T0 + it * 4 + r;
        float v = 0.f;
        if (i < n) {
            float di = rsqrtf(deg[i] + 2.f);
            int idx = i * 64 + c;
            v = di * agg[idx] + 2.f * di * di * xw[idx] + b[c];
            if (act) v = tanhf(v);
            outH[idx] = v;
        }
        if (p) {
            float pc = p[c];
            float hp = (i < n) ? v * pc : 0.f;
            float pp = (r == 0) ? pc * pc : 0.f;
            #pragma unroll
            for (int off = 16; off > 0; off >>= 1) {
                hp += __shfl_down_sync(0xffffffffu, hp, off);
                pp += __shfl_down_sync(0xffffffffu, pp, off);
            }
            int w = tid >> 5, lane = tid & 31;
            if (lane == 0) { part[w] = hp; ppart[w] = pp; }
            __syncthreads();
            if (tid < 4) {
                int ii = T0 + it * 4 + tid;
                if (ii < n) {
                    float dot = part[tid * 2] + part[tid * 2 + 1];
                    float pn = ppart[0] + ppart[1];
                    score[ii] = tanhf(dot * rsqrtf(pn));
                }
            }
        }
    }
    if (!p) return;
    // all-tiles completion -> run select
    __threadfence();
    __syncthreads();
    if (tid == 0) lastAll = (atomicAdd(donectr, 1) == (int)gridDim.x - 1);
    __syncthreads();
    if (lastAll) {
        __threadfence();
        dev_select(score, n, selK, perm, map);
    }
}

__global__ void k_pack(const float* __restrict__ A1v, const int* __restrict__ perm,
                       int* __restrict__ Apt, int* __restrict__ Gpt) {
    int idx = blockIdx.x * blockDim.x + threadIdx.x;
    const int half = KWP * NP2;
    if (idx >= 2 * half) return;
    int sel = (idx >= half) ? 1 : 0;
    int l = idx - sel * half;
    int w = l / NP2, i = l - w * NP2;
    int v = 0;
    if (i < K2) {
        int pi = perm[i];
        if (sel == 0) {
            const float* row = A1v + (size_t)pi * K1;
            #pragma unroll
            for (int q = 0; q < 4; q++) {
                int kq = 4 * w + q;
                int b = (kq < K1) ? (int)row[kq] : 0;
                v |= (b & 0xFF) << (8 * q);
            }
        } else {
            #pragma unroll
            for (int q = 0; q < 4; q++) {
                int kq = 4 * w + q;
                int b = (kq < K1) ? (int)A1v[(size_t)kq * K1 + pi] : 0;
                v |= (b & 0xFF) << (8 * q);
            }
        }
    }
    if (sel == 0) Apt[w * NP2 + i] = v; else Gpt[w * NP2 + i] = v;
}

__global__ void k_dp4aA2(const int* __restrict__ Apt, const int* __restrict__ Gpt,
                         const float* __restrict__ A1v, const int* __restrict__ perm,
                         float* __restrict__ A2, float* deg2) {
    __shared__ int As[8][68], Bs[8][68];
    __shared__ int prs[64], pcs[64];
    __shared__ float csum[64];
    int tid = threadIdx.x;
    int tx = tid & 15, ty = tid >> 4;
    int row0 = blockIdx.y * 64, col0 = blockIdx.x * 64;
    if (tid < 64) { prs[tid] = (row0 + tid < K2) ? perm[row0 + tid] : 0; csum[tid] = 0.f; }
    else if (tid < 128) { int c = tid - 64; pcs[c] = (col0 + c < K2) ? perm[col0 + c] : 0; }
    __syncthreads();
    int acc[4][4] = {};
    for (int k0 = 0; k0 < KWP; k0 += 8) {
        #pragma unroll
        for (int pq = 0; pq < 2; pq++) {
            int li = tid + pq * 256;
            int w = li >> 6, c = li & 63;
            As[w][c] = Apt[(k0 + w) * NP2 + row0 + c];
            Bs[w][c] = Gpt[(k0 + w) * NP2 + col0 + c];
        }
        __syncthreads();
        #pragma unroll
        for (int kk = 0; kk < 8; kk++) {
            int4 a4 = *reinterpret_cast<const int4*>(&As[kk][ty * 4]);
            int4 b4 = *reinterpret_cast<const int4*>(&Bs[kk][tx * 4]);
            int a[4] = {a4.x, a4.y, a4.z, a4.w};
            int b[4] = {b4.x, b4.y, b4.z, b4.w};
            #pragma unroll
            for (int i = 0; i < 4; i++)
                #pragma unroll
                for (int j = 0; j < 4; j++)
                    acc[i][j] = __dp4a(a[i], b[j], acc[i][j]);
        }
        __syncthreads();
    }
    float cj[4] = {0.f, 0.f, 0.f, 0.f};
    #pragma unroll
    for (int i2 = 0; i2 < 4; i2++) {
        int gr = row0 + ty * 4 + i2;
        if (gr >= K2) continue;
        int ar = prs[ty * 4 + i2];
        #pragma unroll
        for (int j = 0; j < 4; j++) {
            int gc = col0 + tx * 4 + j;
            if (gc >= K2) continue;
            float val = (gr == gc) ? 0.f
                      : (float)acc[i2][j] + 2.f * A1v[(size_t)ar * K1 + pcs[tx * 4 + j]];
            A2[(size_t)gr * K2 + gc] = val;
            cj[j] += val;
        }
    }
    #pragma unroll
    for (int j = 0; j < 4; j++) atomicAdd(&csum[tx * 4 + j], cj[j]);
    __syncthreads();
    if (tid < 64 && col0 + tid < K2) atomicAdd(&deg2[col0 + tid], csum[tid]);
}

// ---------------- host orchestration ----------------

extern "C" void kernel_launch(void* const* d_in, const int* in_sizes, int n_in,
                              void* d_out, int out_size) {
    float* fp = nullptr; int* ip = nullptr;
    cudaGetSymbolAddress((void**)&fp, g_fpool);
    cudaGetSymbolAddress((void**)&ip, g_ipool);

    const float* x   = (const float*)d_in[0];
    const int*   ei  = (const int*)  d_in[1];
    const float* W0  = (const float*)d_in[2];
    const float* b0  = (const float*)d_in[3];
    const float* W1  = (const float*)d_in[4];
    const float* b1  = (const float*)d_in[5];
    const float* W2  = (const float*)d_in[6];
    const float* b2  = (const float*)d_in[7];
    const float* p1  = (const float*)d_in[8];
    const float* p2  = (const float*)d_in[9];
    const float* Wu0 = (const float*)d_in[10];
    const float* bu0 = (const float*)d_in[11];
    const float* Wu1 = (const float*)d_in[12];
    const float* bu1 = (const float*)d_in[13];
    float* out = (float*)d_out;

    float *A1 = fp + Z_A1, *AGG1 = fp + Z_AGG1, *AGG2 = fp + Z_AGG2,
          *AGG3 = fp + Z_AGG3, *DEG1 = fp + Z_DEG1, *DEG2 = fp + Z_DEG2,
          *A2 = fp + F_A2, *XW = fp + F_XW, *XS = fp + F_XS,
          *H0 = fp + F_H0, *H1 = fp + F_H1, *H2 = fp + F_H2, *HUP = fp + F_HUP,
          *SC = fp + F_SC;
    int *CNT = ip + IZ_CNT, *COLCNT = ip + IZ_COLCNT, *FILL = ip + IZ_FILL,
        *COLFILL = ip + IZ_COLFILL, *CTR = ip + IZ_CTR,
        *ROWPTR = ip + I_ROWPTR, *COLPTR = ip + I_COLPTR,
        *COLS = ip + I_COLS, *CSRC = ip + I_CSRC, *PERM1 = ip + I_PERM1,
        *PERM2 = ip + I_PERM2, *MAP1 = ip + I_MAP1, *MAP2 = ip + I_MAP2,
        *APT = ip + I_APT, *GPT = ip + I_GPT;

    cudaStream_t s = 0;
    const int TB = 256;
    #define GR(n)  (((n) + TB - 1) / TB)
    #define GR4(n) (((n) + 3) / 4)

    cudaMemsetAsync(fp, 0, ZTOT * sizeof(float), s);
    cudaMemsetAsync(ip, 0, IZTOT * sizeof(int), s);

    // CSR + CSC of A0
    k_count<<<GR(EE), TB, 0, s>>>(ei, CNT, COLCNT);
    k_scan2<<<1, 1024, 0, s>>>(CNT, ROWPTR, COLCNT, COLPTR);
    k_fill<<<GR(EE), TB, 0, s>>>(ei, ROWPTR, COLPTR, FILL, COLFILL, COLS, CSRC);

    // GCN0 + score1 + fused select1
    k_lin0<<<GR4(NN), TB, 0, s>>>(x, W0, COLCNT, XW, XS);
    k_gcn0_sel<<<GR4(NN), TB, 0, s>>>(COLPTR, CSRC, XS, XW, COLCNT, b0, H0, p1,
                                      SC, CTR + 0, PERM1, MAP1);

    // A1 (+DEG1)
    k_bb2<<<GR(EE), TB, 0, s>>>(ei, ROWPTR, COLS, MAP1, A1, DEG1, K1);

    // GCN1: linpool + fused atx/finalize/score/select2
    k_linpool<<<GR4(K1), TB, 0, s>>>(H0, SC, PERM1, W1, DEG1, XW, XS, K1);
    { dim3 g(47, 8);
      k_atxfin<<<g, TB, 0, s>>>(A1, XS, AGG1, K1, XW, DEG1, b1, H1, 1,
                                p2, SC, CTR + 1, CTR + 48, K2, PERM2, MAP2); }

    // A2 via dp4a GEMM (+DEG2)
    k_pack<<<(2 * KWP * NP2 + TB - 1) / TB, TB, 0, s>>>(A1, PERM2, APT, GPT);
    { dim3 g(12, 12); k_dp4aA2<<<g, TB, 0, s>>>(APT, GPT, A1, PERM2, A2, DEG2); }

    // GCN2
    k_linpool<<<GR4(K2), TB, 0, s>>>(H1, SC, PERM2, W2, DEG2, XW, XS, K2);
    { dim3 g(24, 8);
      k_atxfin<<<g, TB, 0, s>>>(A2, XS, AGG2, K2, XW, DEG2, b2, H2, 1,
                                nullptr, nullptr, CTR + 49, nullptr, 0, nullptr, nullptr); }

    // up to level 1
    k_linup64<<<GR4(K1), TB, 0, s>>>(H1, H2, MAP2, Wu0, DEG1, XW, XS, K1);
    { dim3 g(47, 8);
      k_atxfin<<<g, TB, 0, s>>>(A1, XS, AGG3, K1, XW, DEG1, bu0, HUP, 1,
                                nullptr, nullptr, CTR + 73, nullptr, 0, nullptr, nullptr); }

    // up to level 0 (final)
    k_linup16<<<(NN + 15) / 16, TB, 0, s>>>(H0, HUP, MAP1, Wu1, COLCNT, XW, XS);
    k_gcnF<<<(NN + 15) / 16, TB, 0, s>>>(COLPTR, CSRC, XS, XW, COLCNT, bu1, out);

    #undef GR
    #undef GR4
}